// round 8
// baseline (speedup 1.0000x reference)
#include <cuda_runtime.h>

#define B_    4
#define Qn    256
#define Kn    1024
#define Din   256
#define H_    128
#define Vn    256
#define NBLK  148
#define NTHR  512

// Scratch (no cudaMalloc allowed)
__device__ float d_qproj[B_ * Qn * H_];
__device__ float d_kproj[B_ * Kn * H_];
__device__ float d_scores[B_ * Qn * Kn];
__device__ float d_WqT[Din * H_];
__device__ float d_WkT[Din * H_];
__device__ float d_B;
__device__ float d_accp[2][B_ * Qn * Vn];    // split-K partial AV
__device__ float d_sump[2][B_ * Qn];         // split-K partial row sums
__device__ unsigned g_arrive;                // grid barrier state (persists across launches)
__device__ unsigned g_gen;

__device__ __forceinline__ float tanh_fast(float x) {
    float y;
    asm("tanh.approx.f32 %0, %1;" : "=f"(y) : "f"(x));
    return y;
}

// per-half (256-thread) barrier
#define NB(id) asm volatile("bar.sync %0, %1;" :: "r"(id), "r"(256) : "memory")

// Device-wide barrier. All 148 blocks are resident (1/SM by smem size), so
// spinning is safe. Generation counter is monotone across graph replays;
// g_arrive returns to 0 after each episode -> deterministic.
__device__ __forceinline__ void grid_barrier() {
    __threadfence();
    __syncthreads();
    if (threadIdx.x == 0) {
        volatile unsigned* gen = &g_gen;
        const unsigned my = *gen;
        const unsigned old = atomicAdd(&g_arrive, 1u);
        if (old == (unsigned)(gridDim.x - 1)) {
            g_arrive = 0;
            __threadfence();
            *gen = my + 1;
        } else {
            while (*gen == my) { }
            __threadfence();
        }
    }
    __syncthreads();
}

// smem overlays (per half; HALF_SZ covers the largest)
struct TrSm    { float ts[32][33]; };                          //  4224 B
struct ProjSm  { float As[32][17]; float Bs[32][128]; };       // 18560 B
struct ScoreSm { float kt[64][132]; float qs[32 * 128]; float wvs[128]; };  // 50688 B
struct AvSm    { float As[2][16][68]; float Bs[2][64][132]; }; // 76288 B
#define HALF_SZ   76800
#define SMEM_TOTAL (2 * HALF_SZ)

__global__ void __launch_bounds__(NTHR, 1) mega_kernel(
    const float* __restrict__ queries, const float* __restrict__ keys,
    const float* __restrict__ values,  const int* __restrict__ valid_lens,
    const float* __restrict__ Wq, const float* __restrict__ Wk,
    const float* __restrict__ wv, float* __restrict__ out)
{
    extern __shared__ char smraw[];
    const int tid = threadIdx.x;
    const int hh  = tid >> 8;          // half: 0 or 1
    const int t2  = tid & 255;         // tid within half
    const int bar = 1 + hh;            // named barrier id for this half
    char* sm = smraw + hh * HALF_SZ;

    // ===================== P0: W transpose + sum|wv| =====================
    if (blockIdx.x < 32) {
        const int hi = blockIdx.x * 2 + hh;       // 0..63
        TrSm* s = (TrSm*)sm;
        const int mat = hi >> 5, t = hi & 31;
        const int i0 = (t >> 2) * 32, h0 = (t & 3) * 32;
        const float* __restrict__ W = mat ? Wk : Wq;
        float* __restrict__ WT      = mat ? d_WkT : d_WqT;
        const int tx = t2 & 31, ty = t2 >> 5;
        #pragma unroll
        for (int r = 0; r < 4; r++)
            s->ts[ty + 8 * r][tx] = W[(h0 + ty + 8 * r) * Din + i0 + tx];
        NB(bar);
        #pragma unroll
        for (int r = 0; r < 4; r++)
            WT[(i0 + ty + 8 * r) * H_ + h0 + tx] = s->ts[tx][ty + 8 * r];
    } else if (blockIdx.x == 32 && hh == 0 && t2 < 32) {
        float s = 0.f;
        #pragma unroll
        for (int i = 0; i < 4; i++) s += fabsf(wv[t2 + 32 * i]);
        #pragma unroll
        for (int off = 16; off; off >>= 1)
            s += __shfl_xor_sync(0xffffffffu, s, off);
        if (t2 == 0) d_B = s;
    }
    grid_barrier();

    // ===================== P1: projection GEMM =====================
    // 320 half-tiles (BM=16, BN=128, BK=32); hi<64 -> queries, else keys.
    for (int it = blockIdx.x; it < 160; it += NBLK) {
        const int hi = it * 2 + hh;
        const float* X; const float* WT; float* outp; int row0;
        if (hi < 64) { X = queries; WT = d_WqT; outp = d_qproj; row0 = hi * 16; }
        else         { X = keys;    WT = d_WkT; outp = d_kproj; row0 = (hi - 64) * 16; }
        ProjSm* s = (ProjSm*)sm;
        const int tx = t2 & 31, ty = t2 >> 5;
        float acc[2][4] = {};

        for (int k0 = 0; k0 < Din; k0 += 32) {
            if (t2 < 128) {
                const int r = t2 >> 3, f = t2 & 7;
                float4 v = *(const float4*)&X[(row0 + r) * Din + k0 + f * 4];
                s->As[f * 4 + 0][r] = v.x; s->As[f * 4 + 1][r] = v.y;
                s->As[f * 4 + 2][r] = v.z; s->As[f * 4 + 3][r] = v.w;
            }
            #pragma unroll
            for (int i = 0; i < 4; i++) {
                const int idx = t2 + 256 * i;
                const int kk = idx >> 5, f = idx & 31;
                *(float4*)&s->Bs[kk][f * 4] = *(const float4*)&WT[(k0 + kk) * H_ + f * 4];
            }
            NB(bar);
            #pragma unroll
            for (int kk = 0; kk < 32; kk++) {
                const float a0 = s->As[kk][ty * 2 + 0];
                const float a1 = s->As[kk][ty * 2 + 1];
                const float4 bv = *(const float4*)&s->Bs[kk][tx * 4];
                acc[0][0] = fmaf(a0, bv.x, acc[0][0]); acc[0][1] = fmaf(a0, bv.y, acc[0][1]);
                acc[0][2] = fmaf(a0, bv.z, acc[0][2]); acc[0][3] = fmaf(a0, bv.w, acc[0][3]);
                acc[1][0] = fmaf(a1, bv.x, acc[1][0]); acc[1][1] = fmaf(a1, bv.y, acc[1][1]);
                acc[1][2] = fmaf(a1, bv.z, acc[1][2]); acc[1][3] = fmaf(a1, bv.w, acc[1][3]);
            }
            NB(bar);
        }
        #pragma unroll
        for (int m = 0; m < 2; m++) {
            float4 v = make_float4(acc[m][0], acc[m][1], acc[m][2], acc[m][3]);
            *(float4*)&outp[(row0 + ty * 2 + m) * H_ + tx * 4] = v;
        }
    }
    grid_barrier();

    // ===================== P2: scores -> p = exp(score - B) =====================
    const float Bsh = d_B;
    for (int it = blockIdx.x; it < 256; it += NBLK) {
        const int hi = it * 2 + hh;               // 0..511
        const int b   = hi >> 7;
        const int qt  = (hi >> 4) & 7;
        const int ktl = hi & 15;
        const int q0 = qt * 32, k0 = ktl * 64;
        const int valid = valid_lens[b];
        if (k0 >= valid) continue;

        ScoreSm* s = (ScoreSm*)sm;
        const int lane = t2 & 31, w = t2 >> 5;
        {
            const float4* __restrict__ src = (const float4*)(d_qproj + (b * Qn + q0) * H_);
            #pragma unroll
            for (int i = 0; i < 4; i++)
                ((float4*)s->qs)[t2 + 256 * i] = src[t2 + 256 * i];
        }
        if (t2 < 128) s->wvs[t2] = wv[t2];
        #pragma unroll
        for (int i = 0; i < 8; i++) {
            const int idx = t2 + 256 * i;
            const int kl = idx >> 5, f = idx & 31;
            *(float4*)&s->kt[kl][f * 4] =
                *(const float4*)&d_kproj[(b * Kn + k0 + kl) * H_ + f * 4];
        }
        NB(bar);

        const int klh = (w & 1) * 32 + lane;
        const int qb  = (w >> 1) * 8;
        const int kg  = k0 + klh;

        float acc[8] = {};
        #pragma unroll
        for (int h0 = 0; h0 < 128; h0 += 16) {
            const float4 kv0 = *(const float4*)&s->kt[klh][h0 + 0];
            const float4 kv1 = *(const float4*)&s->kt[klh][h0 + 4];
            const float4 kv2 = *(const float4*)&s->kt[klh][h0 + 8];
            const float4 kv3 = *(const float4*)&s->kt[klh][h0 + 12];
            const float4 w0 = *(const float4*)&s->wvs[h0 + 0];
            const float4 w1 = *(const float4*)&s->wvs[h0 + 4];
            const float4 w2 = *(const float4*)&s->wvs[h0 + 8];
            const float4 w3 = *(const float4*)&s->wvs[h0 + 12];
            #pragma unroll
            for (int qi = 0; qi < 8; qi++) {
                const float* __restrict__ qrow = s->qs + (qb + qi) * 128 + h0;
                const float4 q0v = *(const float4*)&qrow[0];
                const float4 q1v = *(const float4*)&qrow[4];
                const float4 q2v = *(const float4*)&qrow[8];
                const float4 q3v = *(const float4*)&qrow[12];
                float a = acc[qi];
                a = fmaf(w0.x, tanh_fast(q0v.x + kv0.x), a);
                a = fmaf(w0.y, tanh_fast(q0v.y + kv0.y), a);
                a = fmaf(w0.z, tanh_fast(q0v.z + kv0.z), a);
                a = fmaf(w0.w, tanh_fast(q0v.w + kv0.w), a);
                a = fmaf(w1.x, tanh_fast(q1v.x + kv1.x), a);
                a = fmaf(w1.y, tanh_fast(q1v.y + kv1.y), a);
                a = fmaf(w1.z, tanh_fast(q1v.z + kv1.z), a);
                a = fmaf(w1.w, tanh_fast(q1v.w + kv1.w), a);
                a = fmaf(w2.x, tanh_fast(q2v.x + kv2.x), a);
                a = fmaf(w2.y, tanh_fast(q2v.y + kv2.y), a);
                a = fmaf(w2.z, tanh_fast(q2v.z + kv2.z), a);
                a = fmaf(w2.w, tanh_fast(q2v.w + kv2.w), a);
                a = fmaf(w3.x, tanh_fast(q3v.x + kv3.x), a);
                a = fmaf(w3.y, tanh_fast(q3v.y + kv3.y), a);
                a = fmaf(w3.z, tanh_fast(q3v.z + kv3.z), a);
                a = fmaf(w3.w, tanh_fast(q3v.w + kv3.w), a);
                acc[qi] = a;
            }
        }
        const bool live = (kg < valid);
        #pragma unroll
        for (int qi = 0; qi < 8; qi++) {
            const float p = live ? __expf(acc[qi] - Bsh) : 0.f;
            d_scores[(b * Qn + q0 + qb + qi) * Kn + kg] = p;
        }
        NB(bar);   // protect smem reuse before next item's staging
    }
    grid_barrier();

    // ===================== P3: AV partials (split-K = 2) =====================
    // 256 half-tiles: sp = spatial (4b x 16qt x 2vt = 128), seg = k-half.
    // Tile 16q x 128v per half (256 threads), microtile 2q x 4v, BK=64.
    if (blockIdx.x < 128) {
        const int hi = blockIdx.x * 2 + hh;       // 0..255
        const int seg = hi & 1;
        const int sp  = hi >> 1;
        const int b  = sp >> 5;
        const int qt = (sp >> 1) & 15;
        const int vt = sp & 1;
        const int q0 = qt * 16, v0 = vt * 128;
        const int kmax = (valid_lens[b] + 63) & ~63;
        const int nPh = kmax >> 6;
        const int halfPh = (nPh + 1) >> 1;
        const int phA = seg ? halfPh : 0;
        const int phB = seg ? nPh : halfPh;

        AvSm* s = (AvSm*)sm;
        const int tx = t2 & 31, ty = t2 >> 5;     // tx: v/4 (0..31), ty: 0..7

        const int ar = t2 >> 4, af = t2 & 15;     // As load: 16 rows x 16 f4
        const float* __restrict__ arow = d_scores + (b * Qn + q0 + ar) * Kn + af * 4;
        const float* __restrict__ vbase =
            values + ((size_t)b * Kn + (t2 >> 5)) * Vn + v0 + (t2 & 31) * 4;

        float4 acc0 = make_float4(0.f, 0.f, 0.f, 0.f);
        float4 acc1 = make_float4(0.f, 0.f, 0.f, 0.f);
        float sum0 = 0.f, sum1 = 0.f;

        if (phA < phB) {
            float4 pa, pb[8];
            pa = *(const float4*)&arow[phA * 64];
            #pragma unroll
            for (int i = 0; i < 8; i++)
                pb[i] = *(const float4*)&vbase[(size_t)(phA * 64 + 8 * i) * Vn];
            *(float4*)&s->As[0][ar][af * 4] = pa;
            #pragma unroll
            for (int i = 0; i < 8; i++)
                *(float4*)&s->Bs[0][(t2 >> 5) + 8 * i][(t2 & 31) * 4] = pb[i];
            NB(bar);

            for (int ph = phA; ph < phB; ph++) {
                const int buf = (ph - phA) & 1;
                if (ph + 1 < phB) {
                    const int k0n = (ph + 1) * 64;
                    pa = *(const float4*)&arow[k0n];
                    #pragma unroll
                    for (int i = 0; i < 8; i++)
                        pb[i] = *(const float4*)&vbase[(size_t)(k0n + 8 * i) * Vn];
                }
                #pragma unroll
                for (int kk4 = 0; kk4 < 16; kk4++) {
                    const float4 a0 = *(const float4*)&s->As[buf][2 * ty + 0][kk4 * 4];
                    const float4 a1 = *(const float4*)&s->As[buf][2 * ty + 1][kk4 * 4];
                    sum0 += (a0.x + a0.y) + (a0.z + a0.w);
                    sum1 += (a1.x + a1.y) + (a1.z + a1.w);
                    {
                        const float4 bv = *(const float4*)&s->Bs[buf][kk4 * 4 + 0][tx * 4];
                        acc0.x = fmaf(a0.x, bv.x, acc0.x); acc0.y = fmaf(a0.x, bv.y, acc0.y);
                        acc0.z = fmaf(a0.x, bv.z, acc0.z); acc0.w = fmaf(a0.x, bv.w, acc0.w);
                        acc1.x = fmaf(a1.x, bv.x, acc1.x); acc1.y = fmaf(a1.x, bv.y, acc1.y);
                        acc1.z = fmaf(a1.x, bv.z, acc1.z); acc1.w = fmaf(a1.x, bv.w, acc1.w);
                    }
                    {
                        const float4 bv = *(const float4*)&s->Bs[buf][kk4 * 4 + 1][tx * 4];
                        acc0.x = fmaf(a0.y, bv.x, acc0.x); acc0.y = fmaf(a0.y, bv.y, acc0.y);
                        acc0.z = fmaf(a0.y, bv.z, acc0.z); acc0.w = fmaf(a0.y, bv.w, acc0.w);
                        acc1.x = fmaf(a1.y, bv.x, acc1.x); acc1.y = fmaf(a1.y, bv.y, acc1.y);
                        acc1.z = fmaf(a1.y, bv.z, acc1.z); acc1.w = fmaf(a1.y, bv.w, acc1.w);
                    }
                    {
                        const float4 bv = *(const float4*)&s->Bs[buf][kk4 * 4 + 2][tx * 4];
                        acc0.x = fmaf(a0.z, bv.x, acc0.x); acc0.y = fmaf(a0.z, bv.y, acc0.y);
                        acc0.z = fmaf(a0.z, bv.z, acc0.z); acc0.w = fmaf(a0.z, bv.w, acc0.w);
                        acc1.x = fmaf(a1.z, bv.x, acc1.x); acc1.y = fmaf(a1.z, bv.y, acc1.y);
                        acc1.z = fmaf(a1.z, bv.z, acc1.z); acc1.w = fmaf(a1.z, bv.w, acc1.w);
                    }
                    {
                        const float4 bv = *(const float4*)&s->Bs[buf][kk4 * 4 + 3][tx * 4];
                        acc0.x = fmaf(a0.w, bv.x, acc0.x); acc0.y = fmaf(a0.w, bv.y, acc0.y);
                        acc0.z = fmaf(a0.w, bv.z, acc0.z); acc0.w = fmaf(a0.w, bv.w, acc0.w);
                        acc1.x = fmaf(a1.w, bv.x, acc1.x); acc1.y = fmaf(a1.w, bv.y, acc1.y);
                        acc1.z = fmaf(a1.w, bv.z, acc1.z); acc1.w = fmaf(a1.w, bv.w, acc1.w);
                    }
                }
                if (ph + 1 < phB) {
                    const int nb = buf ^ 1;
                    *(float4*)&s->As[nb][ar][af * 4] = pa;
                    #pragma unroll
                    for (int i = 0; i < 8; i++)
                        *(float4*)&s->Bs[nb][(t2 >> 5) + 8 * i][(t2 & 31) * 4] = pb[i];
                }
                NB(bar);
            }
        }
        float* ap = &d_accp[seg][(b * Qn + q0 + 2 * ty) * Vn + v0 + tx * 4];
        *(float4*)ap = acc0;
        *(float4*)(ap + Vn) = acc1;
        if (vt == 0 && tx == 0) {
            d_sump[seg][b * Qn + q0 + 2 * ty + 0] = sum0;
            d_sump[seg][b * Qn + q0 + 2 * ty + 1] = sum1;
        }
    }
    grid_barrier();

    // ===================== P4: combine + normalize =====================
    {
        const int n = B_ * Qn * Vn;
        for (int i = blockIdx.x * NTHR + tid; i < n; i += NBLK * NTHR) {
            const int q = i >> 8;
            const float ssum = d_sump[0][q] + d_sump[1][q];
            out[i] = (d_accp[0][i] + d_accp[1][i]) / ssum;
        }
    }
}

extern "C" void kernel_launch(void* const* d_in, const int* in_sizes, int n_in,
                              void* d_out, int out_size) {
    const float* queries    = (const float*)d_in[0];
    const float* keys       = (const float*)d_in[1];
    const float* values     = (const float*)d_in[2];
    const int*   valid_lens = (const int*)  d_in[3];
    const float* W_q        = (const float*)d_in[4];
    const float* W_k        = (const float*)d_in[5];
    const float* w_v        = (const float*)d_in[6];
    float* out              = (float*)d_out;

    static int configured = 0;
    if (!configured) {
        cudaFuncSetAttribute(mega_kernel,
                             cudaFuncAttributeMaxDynamicSharedMemorySize, SMEM_TOTAL);
        configured = 1;
    }
    mega_kernel<<<NBLK, NTHR, SMEM_TOTAL>>>(queries, keys, values, valid_lens,
                                            W_q, W_k, w_v, out);
}

// round 9
// speedup vs baseline: 1.2815x; 1.2815x over previous
#include <cuda_runtime.h>

#define B_    4
#define Qn    256
#define Kn    1024
#define Din   256
#define H_    128
#define Vn    256
#define SPLITK 4

// Scratch (no cudaMalloc allowed)
__device__ float d_qproj[B_ * Qn * H_];          // [b*Q+q][h]
__device__ float d_kproj[B_ * Kn * H_];          // [b*K+k][h]
__device__ float d_scores[B_ * Qn * Kn];         // p = exp(score - B), zero beyond valid
__device__ float d_WqT[Din * H_];                // [i][h]
__device__ float d_WkT[Din * H_];                // [i][h]
__device__ float d_B;                            // exp shift = sum |w_v|
__device__ float d_accp[SPLITK][B_ * Qn * Vn];   // split-K partial AV
__device__ float d_sump[SPLITK][B_ * Qn];        // split-K partial row sums

__device__ __forceinline__ float tanh_fast(float x) {
    float y;
    asm("tanh.approx.f32 %0, %1;" : "=f"(y) : "f"(x));
    return y;
}

// ---------------------------------------------------------------------------
// Kernel 0: transpose W [H,Din] -> WT [Din,H]  (blocks 0..63)
//           block 64: d_B = sum |w_v|
// ---------------------------------------------------------------------------
__global__ __launch_bounds__(256) void transpose_w(const float* __restrict__ Wq,
                                                   const float* __restrict__ Wk,
                                                   const float* __restrict__ wv) {
    const int blk = blockIdx.x;
    if (blk == 64) {
        if (threadIdx.x < 32) {
            float s = 0.f;
            #pragma unroll
            for (int i = 0; i < 4; i++) s += fabsf(wv[threadIdx.x + 32 * i]);
            #pragma unroll
            for (int off = 16; off; off >>= 1)
                s += __shfl_xor_sync(0xffffffffu, s, off);
            if (threadIdx.x == 0) d_B = s;
        }
        return;
    }
    const int mat = blk >> 5;
    const int t   = blk & 31;
    const int i0 = (t >> 2) * 32;
    const int h0 = (t & 3) * 32;
    const float* __restrict__ W = mat ? Wk : Wq;
    float* __restrict__ WT      = mat ? d_WkT : d_WqT;

    __shared__ float ts[32][33];
    const int tx = threadIdx.x & 31, ty = threadIdx.x >> 5;
    #pragma unroll
    for (int r = 0; r < 4; r++)
        ts[ty + 8 * r][tx] = W[(h0 + ty + 8 * r) * Din + i0 + tx];
    __syncthreads();
    #pragma unroll
    for (int r = 0; r < 4; r++)
        WT[(i0 + ty + 8 * r) * H_ + h0 + tx] = ts[tx][ty + 8 * r];
}

// ---------------------------------------------------------------------------
// Kernel 1: projection GEMM.  out[row][h] = dot(X[row,:], WT[:,h])
// BM=16, BN=128(H), BK=32.  256 threads, 2x4 microtile.  grid=320.
// ---------------------------------------------------------------------------
__global__ __launch_bounds__(256) void proj_gemm(const float* __restrict__ Xq,
                                                 const float* __restrict__ Xk) {
    const int blk = blockIdx.x;
    const float* X; const float* WT; float* out; int row0;
    if (blk < 64) { X = Xq; WT = d_WqT; out = d_qproj; row0 = blk * 16; }
    else          { X = Xk; WT = d_WkT; out = d_kproj; row0 = (blk - 64) * 16; }

    __shared__ float As[32][17];
    __shared__ float Bs[32][128];

    const int tid = threadIdx.x;
    const int tx = tid & 31, ty = tid >> 5;
    float acc[2][4] = {};

    for (int k0 = 0; k0 < Din; k0 += 32) {
        if (tid < 128) {
            const int r = tid >> 3, f = tid & 7;
            float4 v = *(const float4*)&X[(row0 + r) * Din + k0 + f * 4];
            As[f * 4 + 0][r] = v.x; As[f * 4 + 1][r] = v.y;
            As[f * 4 + 2][r] = v.z; As[f * 4 + 3][r] = v.w;
        }
        #pragma unroll
        for (int i = 0; i < 4; i++) {
            const int idx = tid + 256 * i;
            const int kk = idx >> 5, f = idx & 31;
            *(float4*)&Bs[kk][f * 4] = *(const float4*)&WT[(k0 + kk) * H_ + f * 4];
        }
        __syncthreads();

        #pragma unroll
        for (int kk = 0; kk < 32; kk++) {
            const float a0 = As[kk][ty * 2 + 0];
            const float a1 = As[kk][ty * 2 + 1];
            const float4 bv = *(const float4*)&Bs[kk][tx * 4];
            acc[0][0] = fmaf(a0, bv.x, acc[0][0]); acc[0][1] = fmaf(a0, bv.y, acc[0][1]);
            acc[0][2] = fmaf(a0, bv.z, acc[0][2]); acc[0][3] = fmaf(a0, bv.w, acc[0][3]);
            acc[1][0] = fmaf(a1, bv.x, acc[1][0]); acc[1][1] = fmaf(a1, bv.y, acc[1][1]);
            acc[1][2] = fmaf(a1, bv.z, acc[1][2]); acc[1][3] = fmaf(a1, bv.w, acc[1][3]);
        }
        __syncthreads();
    }
    #pragma unroll
    for (int m = 0; m < 2; m++) {
        float4 v = make_float4(acc[m][0], acc[m][1], acc[m][2], acc[m][3]);
        *(float4*)&out[(row0 + ty * 2 + m) * H_ + tx * 4] = v;
    }
}

// ---------------------------------------------------------------------------
// Kernel 2: scores -> p = exp(score - B), zero beyond valid.
// Block tile 32q x 64k.  grid = 512.  (unchanged)
// ---------------------------------------------------------------------------
__global__ __launch_bounds__(256) void score_kernel(const int* __restrict__ valid_lens,
                                                    const float* __restrict__ wv) {
    const int blk = blockIdx.x;
    const int b   = blk >> 7;
    const int qt  = (blk >> 4) & 7;
    const int ktl = blk & 15;
    const int q0 = qt * 32, k0 = ktl * 64;
    const int valid = valid_lens[b];
    if (k0 >= valid) return;

    __shared__ float kt_s[64][132];
    __shared__ float qs[32 * 128];
    __shared__ float wvs[128];

    const int tid = threadIdx.x, lane = tid & 31, w = tid >> 5;

    {
        const float4* __restrict__ src = (const float4*)(d_qproj + (b * Qn + q0) * H_);
        #pragma unroll
        for (int i = 0; i < 4; i++)
            ((float4*)qs)[tid + 256 * i] = src[tid + 256 * i];
    }
    if (tid < 128) wvs[tid] = wv[tid];
    #pragma unroll
    for (int i = 0; i < 8; i++) {
        const int idx = tid + 256 * i;
        const int kl = idx >> 5, f = idx & 31;
        *(float4*)&kt_s[kl][f * 4] =
            *(const float4*)&d_kproj[(b * Kn + k0 + kl) * H_ + f * 4];
    }
    const float Bsh = d_B;
    __syncthreads();

    const int klh = (w & 1) * 32 + lane;
    const int qb  = (w >> 1) * 8;
    const int kg  = k0 + klh;

    float acc[8] = {};
    #pragma unroll
    for (int h0 = 0; h0 < 128; h0 += 16) {
        const float4 kv0 = *(const float4*)&kt_s[klh][h0 + 0];
        const float4 kv1 = *(const float4*)&kt_s[klh][h0 + 4];
        const float4 kv2 = *(const float4*)&kt_s[klh][h0 + 8];
        const float4 kv3 = *(const float4*)&kt_s[klh][h0 + 12];
        const float4 w0 = *(const float4*)&wvs[h0 + 0];
        const float4 w1 = *(const float4*)&wvs[h0 + 4];
        const float4 w2 = *(const float4*)&wvs[h0 + 8];
        const float4 w3 = *(const float4*)&wvs[h0 + 12];
        #pragma unroll
        for (int qi = 0; qi < 8; qi++) {
            const float* __restrict__ qrow = qs + (qb + qi) * 128 + h0;
            const float4 q0v = *(const float4*)&qrow[0];
            const float4 q1v = *(const float4*)&qrow[4];
            const float4 q2v = *(const float4*)&qrow[8];
            const float4 q3v = *(const float4*)&qrow[12];
            float a = acc[qi];
            a = fmaf(w0.x, tanh_fast(q0v.x + kv0.x), a);
            a = fmaf(w0.y, tanh_fast(q0v.y + kv0.y), a);
            a = fmaf(w0.z, tanh_fast(q0v.z + kv0.z), a);
            a = fmaf(w0.w, tanh_fast(q0v.w + kv0.w), a);
            a = fmaf(w1.x, tanh_fast(q1v.x + kv1.x), a);
            a = fmaf(w1.y, tanh_fast(q1v.y + kv1.y), a);
            a = fmaf(w1.z, tanh_fast(q1v.z + kv1.z), a);
            a = fmaf(w1.w, tanh_fast(q1v.w + kv1.w), a);
            a = fmaf(w2.x, tanh_fast(q2v.x + kv2.x), a);
            a = fmaf(w2.y, tanh_fast(q2v.y + kv2.y), a);
            a = fmaf(w2.z, tanh_fast(q2v.z + kv2.z), a);
            a = fmaf(w2.w, tanh_fast(q2v.w + kv2.w), a);
            a = fmaf(w3.x, tanh_fast(q3v.x + kv3.x), a);
            a = fmaf(w3.y, tanh_fast(q3v.y + kv3.y), a);
            a = fmaf(w3.z, tanh_fast(q3v.z + kv3.z), a);
            a = fmaf(w3.w, tanh_fast(q3v.w + kv3.w), a);
            acc[qi] = a;
        }
    }

    const bool live = (kg < valid);
    #pragma unroll
    for (int qi = 0; qi < 8; qi++) {
        const float p = live ? __expf(acc[qi] - Bsh) : 0.f;
        d_scores[(b * Qn + q0 + qb + qi) * Kn + kg] = p;
    }
}

// ---------------------------------------------------------------------------
// Kernel 3: AV GEMM partials, split-K = 4.
// grid = 4seg x (4b x 16qt x 4vt) = 1024 blocks, 128 threads.
// Tile 16q x 64v, BK=64, 2q x 4v microtile, double-buffered smem.
// Each segment covers ceil(nPh/4) BK-phases; writes partial acc + row sums.
// ---------------------------------------------------------------------------
__global__ __launch_bounds__(128) void av_gemm_sk(const float* __restrict__ values,
                                                  const int* __restrict__ valid_lens) {
    const int blk = blockIdx.x;
    const int seg = blk >> 8;                 // 0..3
    const int sp  = blk & 255;
    const int b  = sp >> 6;
    const int qt = (sp >> 2) & 15;
    const int vt = sp & 3;
    const int q0 = qt * 16, v0 = vt * 64;
    const int kmax = (valid_lens[b] + 63) & ~63;
    const int nPh = kmax >> 6;
    const int chunk = (nPh + SPLITK - 1) >> 2;
    const int phA = seg * chunk;
    const int phB = min(nPh, phA + chunk);

    __shared__ float As[2][16][68];   // [buf][q][kk]
    __shared__ float Bs[2][64][68];   // [buf][kk][v]

    const int tid = threadIdx.x;
    const int tx = tid & 15, ty = tid >> 4;     // tx: v/4, ty: 0..7

    const float* __restrict__ a0p = d_scores + (b * Qn + q0 + ty)     * Kn + tx * 4;
    const float* __restrict__ a1p = d_scores + (b * Qn + q0 + ty + 8) * Kn + tx * 4;
    const float* __restrict__ vbase = values + ((size_t)b * Kn + ty) * Vn + v0 + tx * 4;

    float4 acc0 = make_float4(0.f, 0.f, 0.f, 0.f);
    float4 acc1 = make_float4(0.f, 0.f, 0.f, 0.f);
    float sum0 = 0.f, sum1 = 0.f;

    if (phA < phB) {
        float4 pa[2], pb[8];
        {
            const int k00 = phA * 64;
            pa[0] = *(const float4*)&a0p[k00];
            pa[1] = *(const float4*)&a1p[k00];
            #pragma unroll
            for (int i = 0; i < 8; i++)
                pb[i] = *(const float4*)&vbase[(size_t)(k00 + 8 * i) * Vn];
        }
        *(float4*)&As[0][ty][tx * 4]     = pa[0];
        *(float4*)&As[0][ty + 8][tx * 4] = pa[1];
        #pragma unroll
        for (int i = 0; i < 8; i++)
            *(float4*)&Bs[0][ty + 8 * i][tx * 4] = pb[i];
        __syncthreads();

        for (int ph = phA; ph < phB; ph++) {
            const int buf = (ph - phA) & 1;
            if (ph + 1 < phB) {
                const int k0n = (ph + 1) * 64;
                pa[0] = *(const float4*)&a0p[k0n];
                pa[1] = *(const float4*)&a1p[k0n];
                #pragma unroll
                for (int i = 0; i < 8; i++)
                    pb[i] = *(const float4*)&vbase[(size_t)(k0n + 8 * i) * Vn];
            }

            #pragma unroll
            for (int kk4 = 0; kk4 < 16; kk4++) {
                const float4 a0 = *(const float4*)&As[buf][2 * ty + 0][kk4 * 4];
                const float4 a1 = *(const float4*)&As[buf][2 * ty + 1][kk4 * 4];
                sum0 += (a0.x + a0.y) + (a0.z + a0.w);
                sum1 += (a1.x + a1.y) + (a1.z + a1.w);
                {
                    const float4 bv = *(const float4*)&Bs[buf][kk4 * 4 + 0][tx * 4];
                    acc0.x = fmaf(a0.x, bv.x, acc0.x); acc0.y = fmaf(a0.x, bv.y, acc0.y);
                    acc0.z = fmaf(a0.x, bv.z, acc0.z); acc0.w = fmaf(a0.x, bv.w, acc0.w);
                    acc1.x = fmaf(a1.x, bv.x, acc1.x); acc1.y = fmaf(a1.x, bv.y, acc1.y);
                    acc1.z = fmaf(a1.x, bv.z, acc1.z); acc1.w = fmaf(a1.x, bv.w, acc1.w);
                }
                {
                    const float4 bv = *(const float4*)&Bs[buf][kk4 * 4 + 1][tx * 4];
                    acc0.x = fmaf(a0.y, bv.x, acc0.x); acc0.y = fmaf(a0.y, bv.y, acc0.y);
                    acc0.z = fmaf(a0.y, bv.z, acc0.z); acc0.w = fmaf(a0.y, bv.w, acc0.w);
                    acc1.x = fmaf(a1.y, bv.x, acc1.x); acc1.y = fmaf(a1.y, bv.y, acc1.y);
                    acc1.z = fmaf(a1.y, bv.z, acc1.z); acc1.w = fmaf(a1.y, bv.w, acc1.w);
                }
                {
                    const float4 bv = *(const float4*)&Bs[buf][kk4 * 4 + 2][tx * 4];
                    acc0.x = fmaf(a0.z, bv.x, acc0.x); acc0.y = fmaf(a0.z, bv.y, acc0.y);
                    acc0.z = fmaf(a0.z, bv.z, acc0.z); acc0.w = fmaf(a0.z, bv.w, acc0.w);
                    acc1.x = fmaf(a1.z, bv.x, acc1.x); acc1.y = fmaf(a1.z, bv.y, acc1.y);
                    acc1.z = fmaf(a1.z, bv.z, acc1.z); acc1.w = fmaf(a1.z, bv.w, acc1.w);
                }
                {
                    const float4 bv = *(const float4*)&Bs[buf][kk4 * 4 + 3][tx * 4];
                    acc0.x = fmaf(a0.w, bv.x, acc0.x); acc0.y = fmaf(a0.w, bv.y, acc0.y);
                    acc0.z = fmaf(a0.w, bv.z, acc0.z); acc0.w = fmaf(a0.w, bv.w, acc0.w);
                    acc1.x = fmaf(a1.w, bv.x, acc1.x); acc1.y = fmaf(a1.w, bv.y, acc1.y);
                    acc1.z = fmaf(a1.w, bv.z, acc1.z); acc1.w = fmaf(a1.w, bv.w, acc1.w);
                }
            }

            if (ph + 1 < phB) {
                const int nb = buf ^ 1;
                *(float4*)&As[nb][ty][tx * 4]     = pa[0];
                *(float4*)&As[nb][ty + 8][tx * 4] = pa[1];
                #pragma unroll
                for (int i = 0; i < 8; i++)
                    *(float4*)&Bs[nb][ty + 8 * i][tx * 4] = pb[i];
            }
            __syncthreads();
        }
    }

    float* ap = &d_accp[seg][(b * Qn + q0 + 2 * ty) * Vn + v0 + tx * 4];
    *(float4*)ap = acc0;
    *(float4*)(ap + Vn) = acc1;
    if (vt == 0 && tx == 0) {
        d_sump[seg][b * Qn + q0 + 2 * ty + 0] = sum0;
        d_sump[seg][b * Qn + q0 + 2 * ty + 1] = sum1;
    }
}

// ---------------------------------------------------------------------------
// Kernel 4: combine split-K partials + normalize.  grid 256 x 256 threads,
// one float4 per thread (65536 f4 = 262144 floats).
// ---------------------------------------------------------------------------
__global__ __launch_bounds__(256) void combine(float* __restrict__ out) {
    const int i4 = blockIdx.x * 256 + threadIdx.x;     // float4 index
    const int q  = i4 >> 6;                            // (i4*4) / 256
    const float ssum = d_sump[0][q] + d_sump[1][q] + d_sump[2][q] + d_sump[3][q];
    const float inv = 1.0f / ssum;
    float4 a = ((const float4*)d_accp[0])[i4];
    const float4 b1 = ((const float4*)d_accp[1])[i4];
    const float4 b2 = ((const float4*)d_accp[2])[i4];
    const float4 b3 = ((const float4*)d_accp[3])[i4];
    a.x = (a.x + b1.x + b2.x + b3.x) * inv;
    a.y = (a.y + b1.y + b2.y + b3.y) * inv;
    a.z = (a.z + b1.z + b2.z + b3.z) * inv;
    a.w = (a.w + b1.w + b2.w + b3.w) * inv;
    ((float4*)out)[i4] = a;
}

extern "C" void kernel_launch(void* const* d_in, const int* in_sizes, int n_in,
                              void* d_out, int out_size) {
    const float* queries    = (const float*)d_in[0];
    const float* keys       = (const float*)d_in[1];
    const float* values     = (const float*)d_in[2];
    const int*   valid_lens = (const int*)  d_in[3];
    const float* W_q        = (const float*)d_in[4];
    const float* W_k        = (const float*)d_in[5];
    const float* w_v        = (const float*)d_in[6];
    float* out              = (float*)d_out;

    transpose_w<<<65, 256>>>(W_q, W_k, w_v);
    proj_gemm<<<320, 256>>>(queries, keys);
    score_kernel<<<512, 256>>>(valid_lens, w_v);
    av_gemm_sk<<<1024, 128>>>(values, valid_lens);
    combine<<<256, 256>>>(out);
}

// round 11
// speedup vs baseline: 1.4457x; 1.1282x over previous
#include <cuda_runtime.h>

#define B_    4
#define Qn    256
#define Kn    1024
#define Din   256
#define H_    128
#define Vn    256
#define NSEG  8

// Scratch (no cudaMalloc allowed)
__device__ float d_qproj[B_ * Qn * H_];          // [b*Q+q][h]
__device__ float d_kproj[B_ * Kn * H_];          // [b*K+k][h]
__device__ float d_scores[B_ * Qn * Kn];         // p = exp(score - B), zero beyond valid
__device__ float d_WqT[Din * H_];                // [i][h]
__device__ float d_WkT[Din * H_];                // [i][h]
__device__ float d_B;                            // exp shift = sum |w_v|
__device__ float d_accp[NSEG][B_ * Qn * Vn];     // chunked partial AV
__device__ float d_sump[NSEG][B_ * Qn];          // chunked partial row sums

__device__ __forceinline__ float tanh_fast(float x) {
    float y;
    asm("tanh.approx.f32 %0, %1;" : "=f"(y) : "f"(x));
    return y;
}

// ---------------------------------------------------------------------------
// Kernel 0: transpose W [H,Din] -> WT [Din,H]  (blocks 0..63)
//           block 64: d_B = sum |w_v|
// ---------------------------------------------------------------------------
__global__ __launch_bounds__(256) void transpose_w(const float* __restrict__ Wq,
                                                   const float* __restrict__ Wk,
                                                   const float* __restrict__ wv) {
    const int blk = blockIdx.x;
    if (blk == 64) {
        if (threadIdx.x < 32) {
            float s = 0.f;
            #pragma unroll
            for (int i = 0; i < 4; i++) s += fabsf(wv[threadIdx.x + 32 * i]);
            #pragma unroll
            for (int off = 16; off; off >>= 1)
                s += __shfl_xor_sync(0xffffffffu, s, off);
            if (threadIdx.x == 0) d_B = s;
        }
        return;
    }
    const int mat = blk >> 5;
    const int t   = blk & 31;
    const int i0 = (t >> 2) * 32;
    const int h0 = (t & 3) * 32;
    const float* __restrict__ W = mat ? Wk : Wq;
    float* __restrict__ WT      = mat ? d_WkT : d_WqT;

    __shared__ float ts[32][33];
    const int tx = threadIdx.x & 31, ty = threadIdx.x >> 5;
    #pragma unroll
    for (int r = 0; r < 4; r++)
        ts[ty + 8 * r][tx] = W[(h0 + ty + 8 * r) * Din + i0 + tx];
    __syncthreads();
    #pragma unroll
    for (int r = 0; r < 4; r++)
        WT[(i0 + ty + 8 * r) * H_ + h0 + tx] = ts[tx][ty + 8 * r];
}

// ---------------------------------------------------------------------------
// Kernel 1: projection GEMM (unchanged).  grid=320.
// ---------------------------------------------------------------------------
__global__ __launch_bounds__(256) void proj_gemm(const float* __restrict__ Xq,
                                                 const float* __restrict__ Xk) {
    const int blk = blockIdx.x;
    const float* X; const float* WT; float* out; int row0;
    if (blk < 64) { X = Xq; WT = d_WqT; out = d_qproj; row0 = blk * 16; }
    else          { X = Xk; WT = d_WkT; out = d_kproj; row0 = (blk - 64) * 16; }

    __shared__ float As[32][17];
    __shared__ float Bs[32][128];

    const int tid = threadIdx.x;
    const int tx = tid & 31, ty = tid >> 5;
    float acc[2][4] = {};

    for (int k0 = 0; k0 < Din; k0 += 32) {
        if (tid < 128) {
            const int r = tid >> 3, f = tid & 7;
            float4 v = *(const float4*)&X[(row0 + r) * Din + k0 + f * 4];
            As[f * 4 + 0][r] = v.x; As[f * 4 + 1][r] = v.y;
            As[f * 4 + 2][r] = v.z; As[f * 4 + 3][r] = v.w;
        }
        #pragma unroll
        for (int i = 0; i < 4; i++) {
            const int idx = tid + 256 * i;
            const int kk = idx >> 5, f = idx & 31;
            *(float4*)&Bs[kk][f * 4] = *(const float4*)&WT[(k0 + kk) * H_ + f * 4];
        }
        __syncthreads();

        #pragma unroll
        for (int kk = 0; kk < 32; kk++) {
            const float a0 = As[kk][ty * 2 + 0];
            const float a1 = As[kk][ty * 2 + 1];
            const float4 bv = *(const float4*)&Bs[kk][tx * 4];
            acc[0][0] = fmaf(a0, bv.x, acc[0][0]); acc[0][1] = fmaf(a0, bv.y, acc[0][1]);
            acc[0][2] = fmaf(a0, bv.z, acc[0][2]); acc[0][3] = fmaf(a0, bv.w, acc[0][3]);
            acc[1][0] = fmaf(a1, bv.x, acc[1][0]); acc[1][1] = fmaf(a1, bv.y, acc[1][1]);
            acc[1][2] = fmaf(a1, bv.z, acc[1][2]); acc[1][3] = fmaf(a1, bv.w, acc[1][3]);
        }
        __syncthreads();
    }
    #pragma unroll
    for (int m = 0; m < 2; m++) {
        float4 v = make_float4(acc[m][0], acc[m][1], acc[m][2], acc[m][3]);
        *(float4*)&out[(row0 + ty * 2 + m) * H_ + tx * 4] = v;
    }
}

// ---------------------------------------------------------------------------
// Kernel 2: scores, STATIC strided schedule over live tiles only.
// grid = 444.  Work index space = all (b, ktl, qt) with ktl*64 < valid[b].
// Block j handles wk = j, j+444, ...  (all live tiles cost identical work,
// so striding is perfectly balanced; no atomics, no queues).
// ---------------------------------------------------------------------------
__global__ __launch_bounds__(256) void score_kernel(const int* __restrict__ valid_lens,
                                                    const float* __restrict__ wv) {
    __shared__ float kt_s[64][132];
    __shared__ float qs[32 * 128];
    __shared__ float wvs[128];

    const int tid = threadIdx.x, lane = tid & 31, w = tid >> 5;

    int vl[4], nkt[4];
    int tot = 0;
    #pragma unroll
    for (int bb = 0; bb < 4; bb++) {
        vl[bb] = valid_lens[bb];
        nkt[bb] = (vl[bb] + 63) >> 6;
        tot += nkt[bb] * 8;
    }
    const float Bsh = d_B;
    if (tid < 128) wvs[tid] = wv[tid];
    __syncthreads();

    for (int wk = blockIdx.x; wk < tot; wk += gridDim.x) {
        // decode (uniform across block; no shared state)
        int rem = wk, b = 0;
        while (b < 3 && rem >= nkt[b] * 8) { rem -= nkt[b] * 8; b++; }
        const int ktl = rem >> 3, qt = rem & 7;
        const int q0 = qt * 32, k0 = ktl * 64;
        const int valid = vl[b];

        // stage tiles
        {
            const float4* __restrict__ src = (const float4*)(d_qproj + (b * Qn + q0) * H_);
            #pragma unroll
            for (int i = 0; i < 4; i++)
                ((float4*)qs)[tid + 256 * i] = src[tid + 256 * i];
        }
        #pragma unroll
        for (int i = 0; i < 8; i++) {
            const int idx = tid + 256 * i;
            const int kl = idx >> 5, f = idx & 31;
            *(float4*)&kt_s[kl][f * 4] =
                *(const float4*)&d_kproj[(b * Kn + k0 + kl) * H_ + f * 4];
        }
        __syncthreads();

        const int klh = (w & 1) * 32 + lane;
        const int qb  = (w >> 1) * 8;
        const int kg  = k0 + klh;

        float acc[8] = {};
        #pragma unroll
        for (int h0 = 0; h0 < 128; h0 += 16) {
            const float4 kv0 = *(const float4*)&kt_s[klh][h0 + 0];
            const float4 kv1 = *(const float4*)&kt_s[klh][h0 + 4];
            const float4 kv2 = *(const float4*)&kt_s[klh][h0 + 8];
            const float4 kv3 = *(const float4*)&kt_s[klh][h0 + 12];
            const float4 w0 = *(const float4*)&wvs[h0 + 0];
            const float4 w1 = *(const float4*)&wvs[h0 + 4];
            const float4 w2 = *(const float4*)&wvs[h0 + 8];
            const float4 w3 = *(const float4*)&wvs[h0 + 12];
            #pragma unroll
            for (int qi = 0; qi < 8; qi++) {
                const float* __restrict__ qrow = qs + (qb + qi) * 128 + h0;
                const float4 q0v = *(const float4*)&qrow[0];
                const float4 q1v = *(const float4*)&qrow[4];
                const float4 q2v = *(const float4*)&qrow[8];
                const float4 q3v = *(const float4*)&qrow[12];
                float a = acc[qi];
                a = fmaf(w0.x, tanh_fast(q0v.x + kv0.x), a);
                a = fmaf(w0.y, tanh_fast(q0v.y + kv0.y), a);
                a = fmaf(w0.z, tanh_fast(q0v.z + kv0.z), a);
                a = fmaf(w0.w, tanh_fast(q0v.w + kv0.w), a);
                a = fmaf(w1.x, tanh_fast(q1v.x + kv1.x), a);
                a = fmaf(w1.y, tanh_fast(q1v.y + kv1.y), a);
                a = fmaf(w1.z, tanh_fast(q1v.z + kv1.z), a);
                a = fmaf(w1.w, tanh_fast(q1v.w + kv1.w), a);
                a = fmaf(w2.x, tanh_fast(q2v.x + kv2.x), a);
                a = fmaf(w2.y, tanh_fast(q2v.y + kv2.y), a);
                a = fmaf(w2.z, tanh_fast(q2v.z + kv2.z), a);
                a = fmaf(w2.w, tanh_fast(q2v.w + kv2.w), a);
                a = fmaf(w3.x, tanh_fast(q3v.x + kv3.x), a);
                a = fmaf(w3.y, tanh_fast(q3v.y + kv3.y), a);
                a = fmaf(w3.z, tanh_fast(q3v.z + kv3.z), a);
                a = fmaf(w3.w, tanh_fast(q3v.w + kv3.w), a);
                acc[qi] = a;
            }
        }

        const bool live = (kg < valid);
        #pragma unroll
        for (int qi = 0; qi < 8; qi++) {
            const float p = live ? __expf(acc[qi] - Bsh) : 0.f;
            d_scores[(b * Qn + q0 + qb + qi) * Kn + kg] = p;
        }
        __syncthreads();   // protect smem restage on next work item
    }
}

// ---------------------------------------------------------------------------
// Kernel 3: AV partials, STATIC strided schedule.  grid = 740, 128 threads.
// Work item = (b, chunk c, qt, vt): BK-phases [2c, min(2c+2, nPh_b)).
// Tile 16q x 64v, 2q x 4v microtile, double-buffered smem.
// Partials to statically-indexed slot c (deterministic).
// ---------------------------------------------------------------------------
__global__ __launch_bounds__(128) void av_gemm_s(const float* __restrict__ values,
                                                 const int* __restrict__ valid_lens) {
    __shared__ float As[2][16][68];
    __shared__ float Bs[2][64][68];

    const int tid = threadIdx.x;
    const int tx = tid & 15, ty = tid >> 4;

    int nPh[4], cb[4];
    int tot = 0;
    #pragma unroll
    for (int bb = 0; bb < 4; bb++) {
        nPh[bb] = ((valid_lens[bb] + 63) & ~63) >> 6;
        cb[bb]  = (nPh[bb] + 1) >> 1;
        tot += 64 * cb[bb];
    }

    for (int wk = blockIdx.x; wk < tot; wk += gridDim.x) {
        int rem = wk, b = 0;
        while (b < 3 && rem >= 64 * cb[b]) { rem -= 64 * cb[b]; b++; }
        const int c  = rem >> 6;
        const int sp = rem & 63;
        const int qt = sp >> 2, vt = sp & 3;
        const int q0 = qt * 16, v0 = vt * 64;
        const int phA = 2 * c;
        const int phB = min(nPh[b], 2 * c + 2);

        const float* __restrict__ a0p = d_scores + (b * Qn + q0 + ty)     * Kn + tx * 4;
        const float* __restrict__ a1p = d_scores + (b * Qn + q0 + ty + 8) * Kn + tx * 4;
        const float* __restrict__ vbase = values + ((size_t)b * Kn + ty) * Vn + v0 + tx * 4;

        float4 acc0 = make_float4(0.f, 0.f, 0.f, 0.f);
        float4 acc1 = make_float4(0.f, 0.f, 0.f, 0.f);
        float sum0 = 0.f, sum1 = 0.f;

        float4 pa[2], pb[8];
        {
            const int k00 = phA * 64;
            pa[0] = *(const float4*)&a0p[k00];
            pa[1] = *(const float4*)&a1p[k00];
            #pragma unroll
            for (int i = 0; i < 8; i++)
                pb[i] = *(const float4*)&vbase[(size_t)(k00 + 8 * i) * Vn];
        }
        *(float4*)&As[0][ty][tx * 4]     = pa[0];
        *(float4*)&As[0][ty + 8][tx * 4] = pa[1];
        #pragma unroll
        for (int i = 0; i < 8; i++)
            *(float4*)&Bs[0][ty + 8 * i][tx * 4] = pb[i];
        __syncthreads();

        for (int ph = phA; ph < phB; ph++) {
            const int buf = (ph - phA) & 1;
            if (ph + 1 < phB) {
                const int k0n = (ph + 1) * 64;
                pa[0] = *(const float4*)&a0p[k0n];
                pa[1] = *(const float4*)&a1p[k0n];
                #pragma unroll
                for (int i = 0; i < 8; i++)
                    pb[i] = *(const float4*)&vbase[(size_t)(k0n + 8 * i) * Vn];
            }

            #pragma unroll
            for (int kk4 = 0; kk4 < 16; kk4++) {
                const float4 a0 = *(const float4*)&As[buf][2 * ty + 0][kk4 * 4];
                const float4 a1 = *(const float4*)&As[buf][2 * ty + 1][kk4 * 4];
                sum0 += (a0.x + a0.y) + (a0.z + a0.w);
                sum1 += (a1.x + a1.y) + (a1.z + a1.w);
                {
                    const float4 bv = *(const float4*)&Bs[buf][kk4 * 4 + 0][tx * 4];
                    acc0.x = fmaf(a0.x, bv.x, acc0.x); acc0.y = fmaf(a0.x, bv.y, acc0.y);
                    acc0.z = fmaf(a0.x, bv.z, acc0.z); acc0.w = fmaf(a0.x, bv.w, acc0.w);
                    acc1.x = fmaf(a1.x, bv.x, acc1.x); acc1.y = fmaf(a1.x, bv.y, acc1.y);
                    acc1.z = fmaf(a1.x, bv.z, acc1.z); acc1.w = fmaf(a1.x, bv.w, acc1.w);
                }
                {
                    const float4 bv = *(const float4*)&Bs[buf][kk4 * 4 + 1][tx * 4];
                    acc0.x = fmaf(a0.y, bv.x, acc0.x); acc0.y = fmaf(a0.y, bv.y, acc0.y);
                    acc0.z = fmaf(a0.y, bv.z, acc0.z); acc0.w = fmaf(a0.y, bv.w, acc0.w);
                    acc1.x = fmaf(a1.y, bv.x, acc1.x); acc1.y = fmaf(a1.y, bv.y, acc1.y);
                    acc1.z = fmaf(a1.y, bv.z, acc1.z); acc1.w = fmaf(a1.y, bv.w, acc1.w);
                }
                {
                    const float4 bv = *(const float4*)&Bs[buf][kk4 * 4 + 2][tx * 4];
                    acc0.x = fmaf(a0.z, bv.x, acc0.x); acc0.y = fmaf(a0.z, bv.y, acc0.y);
                    acc0.z = fmaf(a0.z, bv.z, acc0.z); acc0.w = fmaf(a0.z, bv.w, acc0.w);
                    acc1.x = fmaf(a1.z, bv.x, acc1.x); acc1.y = fmaf(a1.z, bv.y, acc1.y);
                    acc1.z = fmaf(a1.z, bv.z, acc1.z); acc1.w = fmaf(a1.z, bv.w, acc1.w);
                }
                {
                    const float4 bv = *(const float4*)&Bs[buf][kk4 * 4 + 3][tx * 4];
                    acc0.x = fmaf(a0.w, bv.x, acc0.x); acc0.y = fmaf(a0.w, bv.y, acc0.y);
                    acc0.z = fmaf(a0.w, bv.z, acc0.z); acc0.w = fmaf(a0.w, bv.w, acc0.w);
                    acc1.x = fmaf(a1.w, bv.x, acc1.x); acc1.y = fmaf(a1.w, bv.y, acc1.y);
                    acc1.z = fmaf(a1.w, bv.z, acc1.z); acc1.w = fmaf(a1.w, bv.w, acc1.w);
                }
            }

            if (ph + 1 < phB) {
                const int nb = buf ^ 1;
                *(float4*)&As[nb][ty][tx * 4]     = pa[0];
                *(float4*)&As[nb][ty + 8][tx * 4] = pa[1];
                #pragma unroll
                for (int i = 0; i < 8; i++)
                    *(float4*)&Bs[nb][ty + 8 * i][tx * 4] = pb[i];
            }
            __syncthreads();
        }

        float* ap = &d_accp[c][(b * Qn + q0 + 2 * ty) * Vn + v0 + tx * 4];
        *(float4*)ap = acc0;
        *(float4*)(ap + Vn) = acc1;
        if (vt == 0 && tx == 0) {
            d_sump[c][b * Qn + q0 + 2 * ty + 0] = sum0;
            d_sump[c][b * Qn + q0 + 2 * ty + 1] = sum1;
        }
    }
}

// ---------------------------------------------------------------------------
// Kernel 4: combine live chunks + normalize.  grid 256 x 256, float4/thread.
// Only reads slots s < ceil(nPh_b/2)  (stale slots never touched).
// ---------------------------------------------------------------------------
__global__ __launch_bounds__(256) void combine(const int* __restrict__ valid_lens,
                                               float* __restrict__ out) {
    const int i4 = blockIdx.x * 256 + threadIdx.x;     // float4 index
    const int q  = i4 >> 6;
    const int b  = q >> 8;
    const int nPh = ((valid_lens[b] + 63) & ~63) >> 6;
    const int cbn = (nPh + 1) >> 1;

    float4 a = make_float4(0.f, 0.f, 0.f, 0.f);
    float ssum = 0.f;
    for (int s = 0; s < cbn; s++) {
        const float4 p = ((const float4*)d_accp[s])[i4];
        a.x += p.x; a.y += p.y; a.z += p.z; a.w += p.w;
        ssum += d_sump[s][q];
    }
    const float inv = 1.0f / ssum;
    a.x *= inv; a.y *= inv; a.z *= inv; a.w *= inv;
    ((float4*)out)[i4] = a;
}

extern "C" void kernel_launch(void* const* d_in, const int* in_sizes, int n_in,
                              void* d_out, int out_size) {
    const float* queries    = (const float*)d_in[0];
    const float* keys       = (const float*)d_in[1];
    const float* values     = (const float*)d_in[2];
    const int*   valid_lens = (const int*)  d_in[3];
    const float* W_q        = (const float*)d_in[4];
    const float* W_k        = (const float*)d_in[5];
    const float* w_v        = (const float*)d_in[6];
    float* out              = (float*)d_out;

    transpose_w<<<65, 256>>>(W_q, W_k, w_v);
    proj_gemm<<<320, 256>>>(queries, keys);
    score_kernel<<<444, 256>>>(valid_lens, w_v);
    av_gemm_s<<<740, 128>>>(values, valid_lens);
    combine<<<256, 256>>>(valid_lens, out);
}